// round 2
// baseline (speedup 1.0000x reference)
#include <cuda_runtime.h>

// Problem constants
#define QB   64
#define QH   8
#define QM   1024
#define QC   128
#define QMID 64
#define TM   128                  // rows per kf tile
#define NTILES (QM / TM)          // 8
#define NTHREADS 256

// packed fp32x2 FMA (Blackwell): d = a*b + d on both lanes
__device__ __forceinline__ void ffma2(unsigned long long &d, unsigned long long a, unsigned long long b) {
    asm volatile("fma.rn.f32x2 %0, %1, %2, %0;" : "+l"(d) : "l"(a), "l"(b));
}
__device__ __forceinline__ unsigned long long splat2(float v) {
    unsigned long long r;
    asm("mov.b64 %0, {%1, %1};" : "=l"(r) : "f"(v));
    return r;
}
__device__ __forceinline__ float2 unpack2(unsigned long long v) {
    float2 r;
    asm("mov.b64 {%0, %1}, %2;" : "=f"(r.x), "=f"(r.y) : "l"(v));
    return r;
}

// dynamic smem layout (floats):
//  wq      : 128*64  = 8192
//  kf      : 128*128 = 16384
//  att     : 128*64  = 8192
//  logit   : 1024
//  maskf   : 1024
//  wl      : 64
//  bb      : 64
//  pool    : 64
//  red     : 128
//  sc      : 40   (warp scratch [0..7], gmax[32], inv_se[33], cnt int at [35])
#define SMEM_FLOATS (8192 + 16384 + 8192 + 1024 + 1024 + 64 + 64 + 64 + 128 + 40)

extern "C" __global__ void __launch_bounds__(NTHREADS, 1)
scatt_kernel(const float* __restrict__ query,
             const float* __restrict__ key_feat,
             const int*   __restrict__ att_mask,
             const float* __restrict__ value1,
             const float* __restrict__ value2,
             const float* __restrict__ w_basic,
             const float* __restrict__ b_basic,
             const float* __restrict__ w_last,
             const float* __restrict__ b_last,
             const float* __restrict__ w_last2,
             const float* __restrict__ b_last2,
             float* __restrict__ out)
{
    extern __shared__ float sm[];
    float* wq_s    = sm;                      // [k][o]  k:128 o:64
    float* kf_s    = wq_s + 8192;             // [m][quad-swizzled k], 128x128
    float* att_s   = kf_s + 16384;            // [m][o] 128x64 (quad-swizzled)
    float* logit_s = att_s + 8192;            // 1024
    float* maskf_s = logit_s + 1024;          // 1024
    float* wl_s    = maskf_s + 1024;          // 64
    float* bb_s    = wl_s + 64;               // 64
    float* pool_s  = bb_s + 64;               // 64
    float* red_s   = pool_s + 64;             // 128 (q staging, then v2 combine)
    float* sc_s    = red_s + 128;             // 40
    int*   cnt_i   = (int*)(sc_s + 35);

    const int tid = threadIdx.x;
    const int bh  = blockIdx.x;
    const int b   = bh >> 3;
    const int h   = bh & 7;

    const float* qp  = query    + bh * QC;
    const float* kfp = key_feat + (size_t)bh * QM * QC;

    // ---------------- setup ----------------
    if (tid == 0) *cnt_i = 0;
    if (tid < 64) {
        pool_s[tid] = 0.f;
        wl_s[tid]   = w_last[h * QMID + tid];
        bb_s[tid]   = b_basic[h * QMID + tid];
    }
    int cl = 0;
    for (int i = tid; i < QM; i += NTHREADS) {
        int mv = att_mask[b * QM + i];
        maskf_s[i] = (float)mv;
        cl += mv;
    }
    for (int i = tid; i < QC; i += NTHREADS) red_s[i] = qp[i];
    __syncthreads();

    // wq[k][o] = q[k] * w_basic[h][k][o]
    for (int i = tid; i < QC * QMID; i += NTHREADS) {
        int k = i >> 6;
        wq_s[i] = red_s[k] * w_basic[(h * QC + k) * QMID + (i & 63)];
    }
    #pragma unroll
    for (int o = 16; o; o >>= 1) cl += __shfl_xor_sync(~0u, cl, o);
    if ((tid & 31) == 0) atomicAdd(cnt_i, cl);

    const float blast = b_last[h];

    // thread decomposition for GEMM
    const int g  = tid >> 7;        // split-K group (0: k<64, 1: k>=64)
    const int t  = tid & 127;
    const int rg = t >> 3;          // 0..15 (8 rows each)
    const int cg = t & 7;           // 0..7  (cols {4cg..4cg+3} u {32+4cg..+3})
    const int xc = rg & 7;          // kf quad swizzle key
    const int qa = cg ^ (rg & 3);   // att_s swizzled quad

    __syncthreads();

    // per-thread constants for group-1 epilogue
    float wl0[4], wl1[4], bb0[4], bb1[4];
    #pragma unroll
    for (int j = 0; j < 4; ++j) {
        wl0[j] = wl_s[4 * cg + j];      wl1[j] = wl_s[32 + 4 * cg + j];
        bb0[j] = bb_s[4 * cg + j];      bb1[j] = bb_s[32 + 4 * cg + j];
    }
    float pp[8] = {0.f, 0.f, 0.f, 0.f, 0.f, 0.f, 0.f, 0.f};

    // ---------------- main tiles ----------------
    for (int tile = 0; tile < NTILES; ++tile) {
        __syncthreads();   // prev tile's consumers done with kf_s/att_s

        // stage kf tile, quad-swizzled: quad qs = qk ^ ((m>>3)&7)
        {
            const float* src = kfp + (size_t)tile * TM * QC;
            #pragma unroll
            for (int it = 0; it < 16; ++it) {
                int f  = tid + it * NTHREADS;     // float4 index, 4096 total
                int m  = f >> 5;
                int qk = f & 31;
                float4 v = __ldcs((const float4*)(src + (m << 7) + (qk << 2)));
                int qs = qk ^ ((m >> 3) & 7);
                *(float4*)(kf_s + (m << 7) + (qs << 2)) = v;
            }
        }
        __syncthreads();

        // split-K GEMM: this group's k-range [g*64, g*64+64)
        unsigned long long acc[8][4];
        #pragma unroll
        for (int r = 0; r < 8; ++r)
            #pragma unroll
            for (int c = 0; c < 4; ++c) acc[r][c] = 0ULL;

        const float* kfb = kf_s + (rg << 3) * QC;

        #pragma unroll 1
        for (int q = 0; q < 16; ++q) {
            const int qq = (g << 4) + q;        // global quad 0..31
            ulonglong2 bv0[4], bv1[4];
            #pragma unroll
            for (int j = 0; j < 4; ++j) {
                const float* wr = wq_s + ((qq << 2) + j) * QMID + (cg << 2);
                bv0[j] = *(const ulonglong2*)wr;
                bv1[j] = *(const ulonglong2*)(wr + 32);
            }
            float4 a[8];
            const int qs4 = ((qq ^ xc) << 2);
            #pragma unroll
            for (int r = 0; r < 8; ++r)
                a[r] = *(const float4*)(kfb + (r << 7) + qs4);

            #pragma unroll
            for (int j = 0; j < 4; ++j) {
                #pragma unroll
                for (int r = 0; r < 8; ++r) {
                    float av = (j == 0) ? a[r].x : (j == 1) ? a[r].y : (j == 2) ? a[r].z : a[r].w;
                    unsigned long long ap = splat2(av);
                    ffma2(acc[r][0], ap, bv0[j].x);
                    ffma2(acc[r][1], ap, bv0[j].y);
                    ffma2(acc[r][2], ap, bv1[j].x);
                    ffma2(acc[r][3], ap, bv1[j].y);
                }
            }
        }

        // combine split-K halves through att_s, fused epilogue in group 1
        if (g == 0) {
            #pragma unroll
            for (int r = 0; r < 8; ++r) {
                float2 p0 = unpack2(acc[r][0]);
                float2 p1 = unpack2(acc[r][1]);
                float2 p2 = unpack2(acc[r][2]);
                float2 p3 = unpack2(acc[r][3]);
                float* dst = att_s + ((rg << 3) + r) * QMID + (qa << 2);
                *(float4*)dst        = make_float4(p0.x, p0.y, p1.x, p1.y);
                *(float4*)(dst + 32) = make_float4(p2.x, p2.y, p3.x, p3.y);
            }
        }
        __syncthreads();
        if (g == 1) {
            #pragma unroll
            for (int r = 0; r < 8; ++r) {
                const int ml = (rg << 3) + r;
                const int mg = tile * TM + ml;
                const float* srcA = att_s + ml * QMID + (qa << 2);
                float4 u0 = *(const float4*)srcA;
                float4 u1 = *(const float4*)(srcA + 32);
                float2 p0 = unpack2(acc[r][0]);
                float2 p1 = unpack2(acc[r][1]);
                float2 p2 = unpack2(acc[r][2]);
                float2 p3 = unpack2(acc[r][3]);
                float x0 = fmaxf(u0.x + p0.x + bb0[0], 0.f);
                float x1 = fmaxf(u0.y + p0.y + bb0[1], 0.f);
                float x2 = fmaxf(u0.z + p1.x + bb0[2], 0.f);
                float x3 = fmaxf(u0.w + p1.y + bb0[3], 0.f);
                float x4 = fmaxf(u1.x + p2.x + bb1[0], 0.f);
                float x5 = fmaxf(u1.y + p2.y + bb1[1], 0.f);
                float x6 = fmaxf(u1.z + p3.x + bb1[2], 0.f);
                float x7 = fmaxf(u1.w + p3.y + bb1[3], 0.f);

                float lp = x0 * wl0[0] + x1 * wl0[1] + x2 * wl0[2] + x3 * wl0[3]
                         + x4 * wl1[0] + x5 * wl1[1] + x6 * wl1[2] + x7 * wl1[3];

                float mk = maskf_s[mg];
                pp[0] += x0 * mk; pp[1] += x1 * mk; pp[2] += x2 * mk; pp[3] += x3 * mk;
                pp[4] += x4 * mk; pp[5] += x5 * mk; pp[6] += x6 * mk; pp[7] += x7 * mk;

                lp += __shfl_xor_sync(~0u, lp, 1);
                lp += __shfl_xor_sync(~0u, lp, 2);
                lp += __shfl_xor_sync(~0u, lp, 4);
                if (cg == 0) logit_s[mg] = (mk != 0.f) ? (lp + blast) : -1e9f;
            }
        }
    }

    // pool accumulation (masked sums, still unnormalized)
    if (g == 1) {
        #pragma unroll
        for (int j = 0; j < 4; ++j) {
            atomicAdd(&pool_s[(cg << 2) + j],      pp[j]);
            atomicAdd(&pool_s[32 + (cg << 2) + j], pp[4 + j]);
        }
    }
    __syncthreads();

    // ---------------- softmax over logits ----------------
    const float cnt_inv = 1.0f / (float)(*cnt_i);
    if (tid < 64) pool_s[tid] *= cnt_inv;

    float lm = -3.4e38f;
    for (int i = tid; i < QM; i += NTHREADS) lm = fmaxf(lm, logit_s[i]);
    #pragma unroll
    for (int o = 16; o; o >>= 1) lm = fmaxf(lm, __shfl_xor_sync(~0u, lm, o));
    if ((tid & 31) == 0) sc_s[tid >> 5] = lm;
    __syncthreads();
    if (tid < 32) {
        float v = (tid < 8) ? sc_s[tid] : -3.4e38f;
        #pragma unroll
        for (int o = 4; o; o >>= 1) v = fmaxf(v, __shfl_xor_sync(~0u, v, o));
        if (tid == 0) sc_s[32] = v;
    }
    __syncthreads();
    const float gmax = sc_s[32];

    float se = 0.f;
    for (int i = tid; i < QM; i += NTHREADS) {
        float e = __expf(logit_s[i] - gmax);
        logit_s[i] = e;                   // in-place: unnormalized alpha
        se += e;
    }
    #pragma unroll
    for (int o = 16; o; o >>= 1) se += __shfl_xor_sync(~0u, se, o);
    if ((tid & 31) == 0) sc_s[tid >> 5] = se;
    __syncthreads();
    if (tid < 32) {
        float v = (tid < 8) ? sc_s[tid] : 0.f;
        #pragma unroll
        for (int o = 4; o; o >>= 1) v += __shfl_xor_sync(~0u, v, o);
        if (tid == 0) sc_s[33] = 1.0f / v;
    }
    __syncthreads();
    const float inv_se = sc_s[33];

    // ---------------- v2 = alpha^T @ value2, gate, output ----------------
    const int d    = tid & 127;
    const int half = tid >> 7;
    {
        const float* vp = value2 + (size_t)bh * QM * QC + (size_t)(half * 512) * QC + d;
        const float* al = logit_s + half * 512;
        float acc2 = 0.f;
        #pragma unroll 8
        for (int m = 0; m < 512; ++m) acc2 += al[m] * __ldcs(vp + m * QC);
        if (half) red_s[d] = acc2;
        __syncthreads();
        if (!half) {
            float v2v = (acc2 + red_s[d]) * inv_se;
            const float* w2 = w_last2 + (h * QMID) * QC + d;
            float pv = 0.f;
            #pragma unroll 8
            for (int o = 0; o < QMID; ++o) pv += pool_s[o] * w2[o * QC];
            float z   = pv + b_last2[h * QC + d];
            float acv = 1.0f / (1.0f + __expf(-z));
            out[bh * QC + d] = value1[bh * QC + d] * v2v * acv;
        }
    }
}

extern "C" void kernel_launch(void* const* d_in, const int* in_sizes, int n_in,
                              void* d_out, int out_size) {
    const float* query    = (const float*)d_in[0];
    const float* key_feat = (const float*)d_in[1];
    const int*   att_mask = (const int*)  d_in[2];
    const float* value1   = (const float*)d_in[3];
    const float* value2   = (const float*)d_in[4];
    const float* w_basic  = (const float*)d_in[5];
    const float* b_basic  = (const float*)d_in[6];
    const float* w_last   = (const float*)d_in[7];
    const float* b_last   = (const float*)d_in[8];
    const float* w_last2  = (const float*)d_in[9];
    const float* b_last2  = (const float*)d_in[10];
    float* out = (float*)d_out;

    const int smem_bytes = SMEM_FLOATS * (int)sizeof(float);
    cudaFuncSetAttribute(scatt_kernel, cudaFuncAttributeMaxDynamicSharedMemorySize, smem_bytes);
    scatt_kernel<<<QB * QH, NTHREADS, smem_bytes>>>(
        query, key_feat, att_mask, value1, value2,
        w_basic, b_basic, w_last, b_last, w_last2, b_last2, out);
}

// round 3
// speedup vs baseline: 1.2747x; 1.2747x over previous
#include <cuda_runtime.h>

// Problem constants
#define QB   64
#define QH   8
#define QM   1024
#define QC   128
#define QMID 64
#define TM   256                  // rows per kf tile
#define NTILES (QM / TM)          // 4
#define NTHREADS 512

// packed fp32x2 FMA (Blackwell): d = a*b + d on both lanes
__device__ __forceinline__ void ffma2(unsigned long long &d, unsigned long long a, unsigned long long b) {
    asm volatile("fma.rn.f32x2 %0, %1, %2, %0;" : "+l"(d) : "l"(a), "l"(b));
}
__device__ __forceinline__ unsigned long long splat2(float v) {
    unsigned long long r;
    asm("mov.b64 %0, {%1, %1};" : "=l"(r) : "f"(v));
    return r;
}
__device__ __forceinline__ float2 unpack2(unsigned long long v) {
    float2 r;
    asm("mov.b64 {%0, %1}, %2;" : "=f"(r.x), "=f"(r.y) : "l"(v));
    return r;
}

// dynamic smem layout (floats):
//  wq      : 128*64  = 8192   (reused as phase-2 partial buffer 16x128)
//  kf      : 256*128 = 32768  (att partials [256x64] alias the front of this)
//  logit   : 1024
//  maskf   : 1024
//  wl      : 64
//  bb      : 64
//  pool    : 64
//  red     : 128  (q staging)
//  sc      : 40
#define SMEM_FLOATS (8192 + 32768 + 1024 + 1024 + 64 + 64 + 64 + 128 + 40)

extern "C" __global__ void __launch_bounds__(NTHREADS, 1)
scatt_kernel(const float* __restrict__ query,
             const float* __restrict__ key_feat,
             const int*   __restrict__ att_mask,
             const float* __restrict__ value1,
             const float* __restrict__ value2,
             const float* __restrict__ w_basic,
             const float* __restrict__ b_basic,
             const float* __restrict__ w_last,
             const float* __restrict__ b_last,
             const float* __restrict__ w_last2,
             const float* __restrict__ b_last2,
             float* __restrict__ out)
{
    extern __shared__ float sm[];
    float* wq_s    = sm;                      // [k][o]  k:128 o:64   (phase2: partials)
    float* kf_s    = wq_s + 8192;             // [m][quad-swizzled k], 256x128
    float* att_s   = kf_s;                    // ALIAS: 256x64 split-K partials
    float* logit_s = kf_s + 32768;            // 1024
    float* maskf_s = logit_s + 1024;          // 1024
    float* wl_s    = maskf_s + 1024;          // 64
    float* bb_s    = wl_s + 64;               // 64
    float* pool_s  = bb_s + 64;               // 64
    float* red_s   = pool_s + 64;             // 128 (q staging)
    float* sc_s    = red_s + 128;             // 40
    int*   cnt_i   = (int*)(sc_s + 35);

    const int tid = threadIdx.x;
    const int bh  = blockIdx.x;
    const int b   = bh >> 3;
    const int h   = bh & 7;

    const float* qp  = query    + bh * QC;
    const float* kfp = key_feat + (size_t)bh * QM * QC;

    // ---------------- setup ----------------
    if (tid == 0) *cnt_i = 0;
    if (tid < 64) {
        pool_s[tid] = 0.f;
        wl_s[tid]   = w_last[h * QMID + tid];
        bb_s[tid]   = b_basic[h * QMID + tid];
    }
    int cl = 0;
    for (int i = tid; i < QM; i += NTHREADS) {
        int mv = att_mask[b * QM + i];
        maskf_s[i] = (float)mv;
        cl += mv;
    }
    for (int i = tid; i < QC; i += NTHREADS) red_s[i] = qp[i];
    __syncthreads();

    // wq[k][o] = q[k] * w_basic[h][k][o]
    for (int i = tid; i < QC * QMID; i += NTHREADS) {
        int k = i >> 6;
        wq_s[i] = red_s[k] * w_basic[(h * QC + k) * QMID + (i & 63)];
    }
    #pragma unroll
    for (int o = 16; o; o >>= 1) cl += __shfl_xor_sync(~0u, cl, o);
    if ((tid & 31) == 0) atomicAdd(cnt_i, cl);

    const float blast = b_last[h];

    // thread decomposition for GEMM (split-K: 2 groups x 256 threads)
    const int g  = tid >> 8;        // split-K group (0: k<64, 1: k>=64)
    const int t  = tid & 255;
    const int rg = t >> 3;          // 0..31 (8 rows each -> 256 rows)
    const int cg = t & 7;           // 0..7  (cols {4cg..4cg+3} u {32+4cg..+3})
    const int xc = rg & 7;          // kf quad swizzle key
    const int qa = cg ^ (rg & 3);   // att_s swizzled quad

    float pp[8] = {0.f, 0.f, 0.f, 0.f, 0.f, 0.f, 0.f, 0.f};

    // ---------------- main tiles ----------------
    for (int tile = 0; tile < NTILES; ++tile) {
        __syncthreads();   // prev tile epilogue done with att_s (alias of kf_s)

        // stage kf tile (256 rows), quad-swizzled: qs = qk ^ ((m>>3)&7)
        {
            const float* src = kfp + (size_t)tile * TM * QC;
            #pragma unroll
            for (int it = 0; it < 16; ++it) {
                int f  = tid + it * NTHREADS;     // float4 index, 8192 total
                int m  = f >> 5;
                int qk = f & 31;
                float4 v = __ldcs((const float4*)(src + (m << 7) + (qk << 2)));
                int qs = qk ^ ((m >> 3) & 7);
                *(float4*)(kf_s + (m << 7) + (qs << 2)) = v;
            }
        }
        __syncthreads();

        // split-K GEMM: this group's k-range [g*64, g*64+64)
        unsigned long long acc[8][4];
        #pragma unroll
        for (int r = 0; r < 8; ++r)
            #pragma unroll
            for (int c = 0; c < 4; ++c) acc[r][c] = 0ULL;

        const float* kfb = kf_s + (rg << 3) * QC;

        #pragma unroll 1
        for (int q = 0; q < 16; ++q) {
            const int qq = (g << 4) + q;        // global quad 0..31
            float4 a[8];
            const int qs4 = ((qq ^ xc) << 2);
            #pragma unroll
            for (int r = 0; r < 8; ++r)
                a[r] = *(const float4*)(kfb + (r << 7) + qs4);

            #pragma unroll
            for (int j = 0; j < 4; ++j) {
                const float* wr = wq_s + ((qq << 2) + j) * QMID + (cg << 2);
                ulonglong2 bv0 = *(const ulonglong2*)wr;
                ulonglong2 bv1 = *(const ulonglong2*)(wr + 32);
                #pragma unroll
                for (int r = 0; r < 8; ++r) {
                    float av = (j == 0) ? a[r].x : (j == 1) ? a[r].y : (j == 2) ? a[r].z : a[r].w;
                    unsigned long long ap = splat2(av);
                    ffma2(acc[r][0], ap, bv0.x);
                    ffma2(acc[r][1], ap, bv0.y);
                    ffma2(acc[r][2], ap, bv1.x);
                    ffma2(acc[r][3], ap, bv1.y);
                }
            }
        }

        __syncthreads();   // all kf reads finished before writing alias region

        if (g == 0) {
            #pragma unroll
            for (int r = 0; r < 8; ++r) {
                float2 p0 = unpack2(acc[r][0]);
                float2 p1 = unpack2(acc[r][1]);
                float2 p2 = unpack2(acc[r][2]);
                float2 p3 = unpack2(acc[r][3]);
                float* dst = att_s + ((rg << 3) + r) * QMID + (qa << 2);
                *(float4*)dst        = make_float4(p0.x, p0.y, p1.x, p1.y);
                *(float4*)(dst + 32) = make_float4(p2.x, p2.y, p3.x, p3.y);
            }
        }
        __syncthreads();
        if (g == 1) {
            // per-tile epilogue constants (dead during GEMM -> no reg pressure there)
            float wl0[4], wl1[4], bb0[4], bb1[4];
            #pragma unroll
            for (int j = 0; j < 4; ++j) {
                wl0[j] = wl_s[4 * cg + j];      wl1[j] = wl_s[32 + 4 * cg + j];
                bb0[j] = bb_s[4 * cg + j];      bb1[j] = bb_s[32 + 4 * cg + j];
            }
            #pragma unroll
            for (int r = 0; r < 8; ++r) {
                const int ml = (rg << 3) + r;
                const int mg = tile * TM + ml;
                const float* srcA = att_s + ml * QMID + (qa << 2);
                float4 u0 = *(const float4*)srcA;
                float4 u1 = *(const float4*)(srcA + 32);
                float2 p0 = unpack2(acc[r][0]);
                float2 p1 = unpack2(acc[r][1]);
                float2 p2 = unpack2(acc[r][2]);
                float2 p3 = unpack2(acc[r][3]);
                float x0 = fmaxf(u0.x + p0.x + bb0[0], 0.f);
                float x1 = fmaxf(u0.y + p0.y + bb0[1], 0.f);
                float x2 = fmaxf(u0.z + p1.x + bb0[2], 0.f);
                float x3 = fmaxf(u0.w + p1.y + bb0[3], 0.f);
                float x4 = fmaxf(u1.x + p2.x + bb1[0], 0.f);
                float x5 = fmaxf(u1.y + p2.y + bb1[1], 0.f);
                float x6 = fmaxf(u1.z + p3.x + bb1[2], 0.f);
                float x7 = fmaxf(u1.w + p3.y + bb1[3], 0.f);

                float lp = x0 * wl0[0] + x1 * wl0[1] + x2 * wl0[2] + x3 * wl0[3]
                         + x4 * wl1[0] + x5 * wl1[1] + x6 * wl1[2] + x7 * wl1[3];

                float mk = maskf_s[mg];
                pp[0] += x0 * mk; pp[1] += x1 * mk; pp[2] += x2 * mk; pp[3] += x3 * mk;
                pp[4] += x4 * mk; pp[5] += x5 * mk; pp[6] += x6 * mk; pp[7] += x7 * mk;

                lp += __shfl_xor_sync(~0u, lp, 1);
                lp += __shfl_xor_sync(~0u, lp, 2);
                lp += __shfl_xor_sync(~0u, lp, 4);
                if (cg == 0) logit_s[mg] = (mk != 0.f) ? (lp + blast) : -1e9f;
            }
        }
    }

    // pool accumulation (masked sums, still unnormalized)
    if (g == 1) {
        #pragma unroll
        for (int j = 0; j < 4; ++j) {
            atomicAdd(&pool_s[(cg << 2) + j],      pp[j]);
            atomicAdd(&pool_s[32 + (cg << 2) + j], pp[4 + j]);
        }
    }
    __syncthreads();

    // ---------------- softmax over logits ----------------
    const float cnt_inv = 1.0f / (float)(*cnt_i);
    if (tid < 64) pool_s[tid] *= cnt_inv;

    float lm = -3.4e38f;
    for (int i = tid; i < QM; i += NTHREADS) lm = fmaxf(lm, logit_s[i]);
    #pragma unroll
    for (int o = 16; o; o >>= 1) lm = fmaxf(lm, __shfl_xor_sync(~0u, lm, o));
    if ((tid & 31) == 0) sc_s[tid >> 5] = lm;
    __syncthreads();
    if (tid < 32) {
        float v = (tid < 16) ? sc_s[tid] : -3.4e38f;
        #pragma unroll
        for (int o = 8; o; o >>= 1) v = fmaxf(v, __shfl_xor_sync(~0u, v, o));
        if (tid == 0) sc_s[32] = v;
    }
    __syncthreads();
    const float gmax = sc_s[32];

    float se = 0.f;
    for (int i = tid; i < QM; i += NTHREADS) {
        float e = __expf(logit_s[i] - gmax);
        logit_s[i] = e;                   // in-place: unnormalized alpha
        se += e;
    }
    #pragma unroll
    for (int o = 16; o; o >>= 1) se += __shfl_xor_sync(~0u, se, o);
    if ((tid & 31) == 0) sc_s[tid >> 5] = se;
    __syncthreads();
    if (tid < 32) {
        float v = (tid < 16) ? sc_s[tid] : 0.f;
        #pragma unroll
        for (int o = 8; o; o >>= 1) v += __shfl_xor_sync(~0u, v, o);
        if (tid == 0) sc_s[33] = 1.0f / v;
    }
    __syncthreads();
    const float inv_se = sc_s[33];

    // ---------------- v2 = alpha^T @ value2 (16 m-slices x 32 float4 cols) ----
    {
        const int qc    = tid & 31;      // float4 column (4 d's)
        const int slice = tid >> 5;      // 0..15, 64 m each
        const float* vp = value2 + (size_t)bh * QM * QC + (size_t)(slice * 64) * QC + (qc << 2);
        const float* al = logit_s + slice * 64;
        float ax = 0.f, ay = 0.f, az = 0.f, aw = 0.f;
        #pragma unroll 8
        for (int m = 0; m < 64; ++m) {
            float a4 = al[m];
            float4 v = __ldcs((const float4*)(vp + m * QC));
            ax += a4 * v.x; ay += a4 * v.y; az += a4 * v.z; aw += a4 * v.w;
        }
        // partials into wq_s (dead now): [slice][128 d]
        *(float4*)(wq_s + slice * QC + (qc << 2)) = make_float4(ax, ay, az, aw);
    }
    __syncthreads();

    // ---------------- final reduce + channel gate + output ----------------
    if (tid < QC) {
        const int d = tid;
        float v2v = 0.f;
        #pragma unroll
        for (int s = 0; s < 16; ++s) v2v += wq_s[s * QC + d];
        v2v *= inv_se;

        const float* w2 = w_last2 + (h * QMID) * QC + d;
        float pv = 0.f;
        #pragma unroll 8
        for (int o = 0; o < QMID; ++o) pv += pool_s[o] * w2[o * QC];
        float z   = pv + b_last2[h * QC + d];
        float acv = 1.0f / (1.0f + __expf(-z));
        out[bh * QC + d] = value1[bh * QC + d] * v2v * acv;
    }
}

extern "C" void kernel_launch(void* const* d_in, const int* in_sizes, int n_in,
                              void* d_out, int out_size) {
    const float* query    = (const float*)d_in[0];
    const float* key_feat = (const float*)d_in[1];
    const int*   att_mask = (const int*)  d_in[2];
    const float* value1   = (const float*)d_in[3];
    const float* value2   = (const float*)d_in[4];
    const float* w_basic  = (const float*)d_in[5];
    const float* b_basic  = (const float*)d_in[6];
    const float* w_last   = (const float*)d_in[7];
    const float* b_last   = (const float*)d_in[8];
    const float* w_last2  = (const float*)d_in[9];
    const float* b_last2  = (const float*)d_in[10];
    float* out = (float*)d_out;

    const int smem_bytes = SMEM_FLOATS * (int)sizeof(float);
    cudaFuncSetAttribute(scatt_kernel, cudaFuncAttributeMaxDynamicSharedMemorySize, smem_bytes);
    scatt_kernel<<<QB * QH, NTHREADS, smem_bytes>>>(
        query, key_feat, att_mask, value1, value2,
        w_basic, b_basic, w_last, b_last, w_last2, b_last2, out);
}

// round 5
// speedup vs baseline: 1.4721x; 1.1549x over previous
#include <cuda_runtime.h>
#include <cstdint>

// Problem constants
#define QB   64
#define QH   8
#define QM   1024
#define QC   128
#define QMID 64
#define TM   128                  // rows per kf tile
#define NTILES (QM / TM)          // 8
#define NTHREADS 256

// packed fp32x2 FMA (Blackwell): d = a*b + d on both lanes
__device__ __forceinline__ void ffma2(unsigned long long &d, unsigned long long a, unsigned long long b) {
    asm volatile("fma.rn.f32x2 %0, %1, %2, %0;" : "+l"(d) : "l"(a), "l"(b));
}
__device__ __forceinline__ unsigned long long splat2(float v) {
    unsigned long long r;
    asm("mov.b64 %0, {%1, %1};" : "=l"(r) : "f"(v));
    return r;
}
__device__ __forceinline__ float2 unpack2(unsigned long long v) {
    float2 r;
    asm("mov.b64 {%0, %1}, %2;" : "=f"(r.x), "=f"(r.y) : "l"(v));
    return r;
}
static __device__ __forceinline__ uint32_t smem_u32(const void* p) {
    uint32_t a;
    asm("{ .reg .u64 t; cvta.to.shared.u64 t, %1; cvt.u32.u64 %0, t; }" : "=r"(a) : "l"(p));
    return a;
}
static __device__ __forceinline__ void cp_async16(uint32_t dst, const void* src) {
    asm volatile("cp.async.cg.shared.global [%0], [%1], 16;" :: "r"(dst), "l"(src) : "memory");
}
#define CP_COMMIT() asm volatile("cp.async.commit_group;" ::: "memory")
#define CP_WAIT0()  asm volatile("cp.async.wait_group 0;" ::: "memory")

// dynamic smem layout (floats):
//  wq      : 128*64  = 8192   (phase2: partial buffer 8x128)
//  kf      : 128*128 = 16384  (att partials [128x64] alias the front)
//  logit   : 1024
//  maskf   : 1024
//  wl/bb/pool : 64*3
//  red     : 128  (q staging)
//  sc      : 40
#define SMEM_FLOATS (8192 + 16384 + 1024 + 1024 + 64 + 64 + 64 + 128 + 40)

extern "C" __global__ void __launch_bounds__(NTHREADS, 2)
scatt_kernel(const float* __restrict__ query,
             const float* __restrict__ key_feat,
             const int*   __restrict__ att_mask,
             const float* __restrict__ value1,
             const float* __restrict__ value2,
             const float* __restrict__ w_basic,
             const float* __restrict__ b_basic,
             const float* __restrict__ w_last,
             const float* __restrict__ b_last,
             const float* __restrict__ w_last2,
             const float* __restrict__ b_last2,
             float* __restrict__ out)
{
    extern __shared__ float sm[];
    float* wq_s    = sm;                      // [k][o]  k:128 o:64
    float* kf_s    = wq_s + 8192;             // [m][quad-swizzled k], 128x128
    float* att_s   = kf_s;                    // ALIAS: 128x64 split-K partials
    float* logit_s = kf_s + 16384;            // 1024
    float* maskf_s = logit_s + 1024;          // 1024
    float* wl_s    = maskf_s + 1024;          // 64
    float* bb_s    = wl_s + 64;               // 64
    float* pool_s  = bb_s + 64;               // 64
    float* red_s   = pool_s + 64;             // 128 (q staging)
    float* sc_s    = red_s + 128;             // 40
    int*   cnt_i   = (int*)(sc_s + 35);

    const uint32_t kf_addr = smem_u32(kf_s);

    const int tid = threadIdx.x;
    const int bh  = blockIdx.x;
    const int b   = bh >> 3;
    const int h   = bh & 7;

    const float* qp  = query    + bh * QC;
    const float* kfp = key_feat + (size_t)bh * QM * QC;

    // ---------------- setup ----------------
    if (tid == 0) *cnt_i = 0;
    if (tid < 64) {
        pool_s[tid] = 0.f;
        wl_s[tid]   = w_last[h * QMID + tid];
        bb_s[tid]   = b_basic[h * QMID + tid];
    }
    int cl = 0;
    for (int i = tid; i < QM; i += NTHREADS) {
        int mv = att_mask[b * QM + i];
        maskf_s[i] = (float)mv;
        cl += mv;
    }
    for (int i = tid; i < QC; i += NTHREADS) red_s[i] = qp[i];
    __syncthreads();

    // wq[k][o] = q[k] * w_basic[h][k][o]
    for (int i = tid; i < QC * QMID; i += NTHREADS) {
        int k = i >> 6;
        wq_s[i] = red_s[k] * w_basic[(h * QC + k) * QMID + (i & 63)];
    }
    #pragma unroll
    for (int o = 16; o; o >>= 1) cl += __shfl_xor_sync(~0u, cl, o);
    if ((tid & 31) == 0) atomicAdd(cnt_i, cl);

    const float blast = b_last[h];

    // thread decomposition for GEMM (split-K: 2 groups x 128 threads)
    const int g  = tid >> 7;        // split-K group (0: k<64, 1: k>=64)
    const int t  = tid & 127;
    const int rg = t >> 3;          // 0..15 (8 rows each -> 128 rows)
    const int cg = t & 7;           // 0..7  (cols {4cg..4cg+3} u {32+4cg..+3})
    const int xc = rg & 7;          // kf quad swizzle key
    const int qa = cg ^ (rg & 3);   // att_s swizzled quad

    float pp[8] = {0.f, 0.f, 0.f, 0.f, 0.f, 0.f, 0.f, 0.f};

    // ---------------- main tiles ----------------
    for (int tile = 0; tile < NTILES; ++tile) {
        __syncthreads();   // prev tile epilogue done with att_s (alias of kf_s)

        // stage kf tile via cp.async, quad-swizzled: qs = qk ^ ((m>>3)&7)
        {
            const float* src = kfp + (size_t)tile * TM * QC;
            #pragma unroll
            for (int it = 0; it < 16; ++it) {
                int f  = tid + it * NTHREADS;     // float4 index, 4096 total
                int m  = f >> 5;
                int qk = f & 31;
                int qs = qk ^ ((m >> 3) & 7);
                cp_async16(kf_addr + (uint32_t)(((m << 7) + (qs << 2)) << 2),
                           src + (m << 7) + (qk << 2));
            }
            CP_COMMIT();
            CP_WAIT0();
        }
        __syncthreads();

        // split-K GEMM: this group's k-range [g*64, g*64+64)
        unsigned long long acc[8][4];
        #pragma unroll
        for (int r = 0; r < 8; ++r)
            #pragma unroll
            for (int c = 0; c < 4; ++c) acc[r][c] = 0ULL;

        const float* kfb = kf_s + (rg << 3) * QC;

        #pragma unroll 1
        for (int q = 0; q < 16; ++q) {
            const int qq = (g << 4) + q;        // global quad 0..31
            float4 a[8];
            const int qs4 = ((qq ^ xc) << 2);
            #pragma unroll
            for (int r = 0; r < 8; ++r)
                a[r] = *(const float4*)(kfb + (r << 7) + qs4);

            #pragma unroll
            for (int j = 0; j < 4; ++j) {
                const float* wr = wq_s + ((qq << 2) + j) * QMID + (cg << 2);
                ulonglong2 bv0 = *(const ulonglong2*)wr;
                ulonglong2 bv1 = *(const ulonglong2*)(wr + 32);
                #pragma unroll
                for (int r = 0; r < 8; ++r) {
                    float av = (j == 0) ? a[r].x : (j == 1) ? a[r].y : (j == 2) ? a[r].z : a[r].w;
                    unsigned long long ap = splat2(av);
                    ffma2(acc[r][0], ap, bv0.x);
                    ffma2(acc[r][1], ap, bv0.y);
                    ffma2(acc[r][2], ap, bv1.x);
                    ffma2(acc[r][3], ap, bv1.y);
                }
            }
        }

        __syncthreads();   // all kf reads finished before writing alias region

        if (g == 0) {
            #pragma unroll
            for (int r = 0; r < 8; ++r) {
                float2 p0 = unpack2(acc[r][0]);
                float2 p1 = unpack2(acc[r][1]);
                float2 p2 = unpack2(acc[r][2]);
                float2 p3 = unpack2(acc[r][3]);
                float* dst = att_s + ((rg << 3) + r) * QMID + (qa << 2);
                *(float4*)dst        = make_float4(p0.x, p0.y, p1.x, p1.y);
                *(float4*)(dst + 32) = make_float4(p2.x, p2.y, p3.x, p3.y);
            }
        }
        __syncthreads();
        if (g == 1) {
            float wl0[4], wl1[4], bb0[4], bb1[4];
            #pragma unroll
            for (int j = 0; j < 4; ++j) {
                wl0[j] = wl_s[4 * cg + j];      wl1[j] = wl_s[32 + 4 * cg + j];
                bb0[j] = bb_s[4 * cg + j];      bb1[j] = bb_s[32 + 4 * cg + j];
            }
            #pragma unroll
            for (int r = 0; r < 8; ++r) {
                const int ml = (rg << 3) + r;
                const int mg = tile * TM + ml;
                const float* srcA = att_s + ml * QMID + (qa << 2);
                float4 u0 = *(const float4*)srcA;
                float4 u1 = *(const float4*)(srcA + 32);
                float2 p0 = unpack2(acc[r][0]);
                float2 p1 = unpack2(acc[r][1]);
                float2 p2 = unpack2(acc[r][2]);
                float2 p3 = unpack2(acc[r][3]);
                float x0 = fmaxf(u0.x + p0.x + bb0[0], 0.f);
                float x1 = fmaxf(u0.y + p0.y + bb0[1], 0.f);
                float x2 = fmaxf(u0.z + p1.x + bb0[2], 0.f);
                float x3 = fmaxf(u0.w + p1.y + bb0[3], 0.f);
                float x4 = fmaxf(u1.x + p2.x + bb1[0], 0.f);
                float x5 = fmaxf(u1.y + p2.y + bb1[1], 0.f);
                float x6 = fmaxf(u1.z + p3.x + bb1[2], 0.f);
                float x7 = fmaxf(u1.w + p3.y + bb1[3], 0.f);

                float lp = x0 * wl0[0] + x1 * wl0[1] + x2 * wl0[2] + x3 * wl0[3]
                         + x4 * wl1[0] + x5 * wl1[1] + x6 * wl1[2] + x7 * wl1[3];

                float mk = maskf_s[mg];
                pp[0] += x0 * mk; pp[1] += x1 * mk; pp[2] += x2 * mk; pp[3] += x3 * mk;
                pp[4] += x4 * mk; pp[5] += x5 * mk; pp[6] += x6 * mk; pp[7] += x7 * mk;

                lp += __shfl_xor_sync(~0u, lp, 1);
                lp += __shfl_xor_sync(~0u, lp, 2);
                lp += __shfl_xor_sync(~0u, lp, 4);
                if (cg == 0) logit_s[mg] = (mk != 0.f) ? (lp + blast) : -1e9f;
            }
        }
    }

    // pool accumulation (masked sums, still unnormalized)
    if (g == 1) {
        #pragma unroll
        for (int j = 0; j < 4; ++j) {
            atomicAdd(&pool_s[(cg << 2) + j],      pp[j]);
            atomicAdd(&pool_s[32 + (cg << 2) + j], pp[4 + j]);
        }
    }
    __syncthreads();

    // ---------------- softmax over logits ----------------
    const float cnt_inv = 1.0f / (float)(*cnt_i);
    if (tid < 64) pool_s[tid] *= cnt_inv;

    float lm = -3.4e38f;
    for (int i = tid; i < QM; i += NTHREADS) lm = fmaxf(lm, logit_s[i]);
    #pragma unroll
    for (int o = 16; o; o >>= 1) lm = fmaxf(lm, __shfl_xor_sync(~0u, lm, o));
    if ((tid & 31) == 0) sc_s[tid >> 5] = lm;
    __syncthreads();
    if (tid < 32) {
        float v = (tid < 8) ? sc_s[tid] : -3.4e38f;
        #pragma unroll
        for (int o = 4; o; o >>= 1) v = fmaxf(v, __shfl_xor_sync(~0u, v, o));
        if (tid == 0) sc_s[32] = v;
    }
    __syncthreads();
    const float gmax = sc_s[32];

    float se = 0.f;
    for (int i = tid; i < QM; i += NTHREADS) {
        float e = __expf(logit_s[i] - gmax);
        logit_s[i] = e;                   // in-place: unnormalized alpha
        se += e;
    }
    #pragma unroll
    for (int o = 16; o; o >>= 1) se += __shfl_xor_sync(~0u, se, o);
    if ((tid & 31) == 0) sc_s[tid >> 5] = se;
    __syncthreads();
    if (tid < 32) {
        float v = (tid < 8) ? sc_s[tid] : 0.f;
        #pragma unroll
        for (int o = 4; o; o >>= 1) v += __shfl_xor_sync(~0u, v, o);
        if (tid == 0) sc_s[33] = 1.0f / v;
    }
    __syncthreads();
    const float inv_se = sc_s[33];

    // ---------------- v2 = alpha^T @ value2 (8 m-slices x 32 float4 cols) ----
    {
        const int qc    = tid & 31;      // float4 column (4 d's)
        const int slice = tid >> 5;      // 0..7, 128 m each
        const float* vp = value2 + (size_t)bh * QM * QC + (size_t)(slice * 128) * QC + (qc << 2);
        const float* al = logit_s + slice * 128;
        float ax = 0.f, ay = 0.f, az = 0.f, aw = 0.f;
        #pragma unroll 8
        for (int m = 0; m < 128; ++m) {
            float a4 = al[m];
            float4 v = __ldcs((const float4*)(vp + m * QC));
            ax += a4 * v.x; ay += a4 * v.y; az += a4 * v.z; aw += a4 * v.w;
        }
        // partials into wq_s (dead now): [slice][128 d]
        *(float4*)(wq_s + slice * QC + (qc << 2)) = make_float4(ax, ay, az, aw);
    }
    __syncthreads();

    // ---------------- final reduce + channel gate + output ----------------
    if (tid < QC) {
        const int d = tid;
        float v2v = 0.f;
        #pragma unroll
        for (int s = 0; s < 8; ++s) v2v += wq_s[s * QC + d];
        v2v *= inv_se;

        const float* w2 = w_last2 + (h * QMID) * QC + d;
        float pv = 0.f;
        #pragma unroll 8
        for (int o = 0; o < QMID; ++o) pv += pool_s[o] * w2[o * QC];
        float z   = pv + b_last2[h * QC + d];
        float acv = 1.0f / (1.0f + __expf(-z));
        out[bh * QC + d] = value1[bh * QC + d] * v2v * acv;
    }
}

extern "C" void kernel_launch(void* const* d_in, const int* in_sizes, int n_in,
                              void* d_out, int out_size) {
    const float* query    = (const float*)d_in[0];
    const float* key_feat = (const float*)d_in[1];
    const int*   att_mask = (const int*)  d_in[2];
    const float* value1   = (const float*)d_in[3];
    const float* value2   = (const float*)d_in[4];
    const float* w_basic  = (const float*)d_in[5];
    const float* b_basic  = (const float*)d_in[6];
    const float* w_last   = (const float*)d_in[7];
    const float* b_last   = (const float*)d_in[8];
    const float* w_last2  = (const float*)d_in[9];
    const float* b_last2  = (const float*)d_in[10];
    float* out = (float*)d_out;

    const int smem_bytes = SMEM_FLOATS * (int)sizeof(float);
    cudaFuncSetAttribute(scatt_kernel, cudaFuncAttributeMaxDynamicSharedMemorySize, smem_bytes);
    scatt_kernel<<<QB * QH, NTHREADS, smem_bytes>>>(
        query, key_feat, att_mask, value1, value2,
        w_basic, b_basic, w_last, b_last, w_last2, b_last2, out);
}